// round 16
// baseline (speedup 1.0000x reference)
#include <cuda_runtime.h>

// ---------------------------------------------------------------------------
// RMSPELoss: per-row permutation-invariant RMSE between logits[:, :4] (DoA
// estimates, radians) and the angles of the 4 one-hot label positions.
//
//   inputs  : d_in[0] = logits  float32 [131072, 181]
//             d_in[1] = labels  int32   [131072, 181]  (exactly 4 ones/row)
//   output  : mean over rows of sqrt(min_perm total / 4)
//
// R13: geometry tune. Same algorithm as R12 (flat int4 tile scan + smem
// scatter + thread-per-row 2+2 assignment DP + fused deterministic
// reduction) with TILE=64 / 128 threads / 2048 blocks: 13.8 blocks/SM
// (16 resident fit exactly in the register file) for better SM balance and
// a smaller tail quantum. Phase-B logit loads hoisted above the label scan
// so their latency hides under the streaming phase.
// ---------------------------------------------------------------------------

constexpr int   BATCH    = 131072;
constexpr int   NC       = 181;
constexpr int   TILE     = 64;                  // rows per block
constexpr int   NTHREAD  = 128;
constexpr int   NBLOCK   = BATCH / TILE;        // 2048
constexpr int   TILE_I4  = TILE * NC / 4;       // 2896 int4 per tile (exact)
// 2896 = 128*22 + 80  ->  20 batched sweeps + 2 full + 1 guarded (tid<80)
constexpr int   TAIL     = TILE_I4 - 22 * NTHREAD;      // 80

constexpr float PI_F      = 3.14159265358979323846f;
constexpr float TWO_PI_F  = 6.283185307179586f;
constexpr float INV_2PI_F = 0.15915494309189535f;    // 1/(2*pi)
constexpr float DEG2RAD_F = 0.017453292519943295f;   // pi/180
// d - (p-90)*deg2rad + pi == fma(p, -deg2rad, d + SHIFT)
constexpr float SHIFT_F   = 90.0f * DEG2RAD_F + PI_F;

// Static scratch (no allocation allowed).
__device__ float    g_partials[NBLOCK];
__device__ unsigned g_count = 0;                // self-resets each launch

// squared wrapped difference; bi = d_i + SHIFT already folded.
__device__ __forceinline__ float sqwrap2(float bi, float pj) {
    float x = fmaf(pj, -DEG2RAD_F, bi);
    float q = floorf(x * INV_2PI_F);
    float w = fmaf(-q, TWO_PI_F, x) - PI_F;
    return w * w;
}

__global__ __launch_bounds__(NTHREAD)
void rmspe_kernel(const float* __restrict__ logits, const int* __restrict__ labels,
                  float* __restrict__ out, int out_size)
{
    __shared__ int      s_cnt[TILE];
    __shared__ unsigned s_posw[TILE];
    __shared__ float    s_red[NTHREAD];
    __shared__ int      s_last;

    const int tid = threadIdx.x;
    const int r0  = blockIdx.x * TILE;

    if (tid < TILE) s_cnt[tid] = 0;

    // ---- hoisted Phase-B logit loads (latency hides under the scan) ----
    float b0 = 0.f, b1 = 0.f, b2 = 0.f, b3 = 0.f;
    if (tid < TILE) {
        const float* lg = logits + (long)(r0 + tid) * NC;
        b0 = __ldcs(lg)     + SHIFT_F;
        b1 = __ldcs(lg + 1) + SHIFT_F;
        b2 = __ldcs(lg + 2) + SHIFT_F;
        b3 = __ldcs(lg + 3) + SHIFT_F;
    }
    __syncthreads();

    unsigned char* s_posb = (unsigned char*)s_posw;
    const int4* base = (const int4*)(labels + (long)r0 * NC);   // 16B aligned

    // ---- Phase A: flat vectorized scan, scatter one-positions ----
    auto emit = [&](int f) {                     // f = flat int index in tile
        unsigned rr = (unsigned)f / 181u;        // row within tile
        unsigned cc = (unsigned)f - rr * 181u;   // column (0..180)
        int rank = atomicAdd(&s_cnt[rr], 1);
        s_posb[rr * 4 + rank] = (unsigned char)cc;
    };
    auto sift = [&](int4 w, int i4) {            // i4 = int4 index in tile
        if (w.x | w.y | w.z | w.w) {
            int f = i4 * 4;
            if (w.x) emit(f);
            if (w.y) emit(f + 1);
            if (w.z) emit(f + 2);
            if (w.w) emit(f + 3);
        }
    };

    #pragma unroll 1
    for (int j = 0; j < 20; j += 5) {
        int4 v[5];
        #pragma unroll
        for (int u = 0; u < 5; u++)
            v[u] = __ldcs(base + tid + NTHREAD * (j + u));
        #pragma unroll
        for (int u = 0; u < 5; u++)
            sift(v[u], tid + NTHREAD * (j + u));
    }
    {
        int4 v20 = __ldcs(base + tid + NTHREAD * 20);
        int4 v21 = __ldcs(base + tid + NTHREAD * 21);
        int4 v22 = make_int4(0, 0, 0, 0);
        if (tid < TAIL) v22 = __ldcs(base + tid + NTHREAD * 22);
        sift(v20, tid + NTHREAD * 20);
        sift(v21, tid + NTHREAD * 21);
        sift(v22, tid + NTHREAD * 22);
    }
    __syncthreads();

    // ---- Phase B: threads 0-63, one row each: cost matrix + 2+2 DP ----
    float rmse = 0.0f;
    if (tid < TILE) {
        const unsigned pw = s_posw[tid];
        float pj[4];
        pj[0] = (float)( pw        & 0xFFu);
        pj[1] = (float)((pw >>  8) & 0xFFu);
        pj[2] = (float)((pw >> 16) & 0xFFu);
        pj[3] = (float)((pw >> 24) & 0xFFu);

        float C[4][4];
        #pragma unroll
        for (int j = 0; j < 4; j++) {
            C[0][j] = sqwrap2(b0, pj[j]);
            C[1][j] = sqwrap2(b1, pj[j]);
            C[2][j] = sqwrap2(b2, pj[j]);
            C[3][j] = sqwrap2(b3, pj[j]);
        }

        // min over all 24 perms = min over 6 unordered column pairs for
        // rows {0,1} x 2 orderings x 2 orderings of the complement.
        float best = 3.4e38f;
        #pragma unroll
        for (int s = 0; s < 6; s++) {
            const int a = (s < 3) ? 0 : (s < 5) ? 1 : 2;
            const int b = (s == 0) ? 1 : (s == 1 || s == 3) ? 2 : 3;
            const int c = (s == 5) ? 0 : (s >= 3) ? 0 : (s == 0) ? 2 : 1;
            const int d = (s == 0) ? 3 : (s == 1) ? 3 : (s == 2) ? 2 :
                          (s == 3) ? 3 : (s == 4) ? 2 : 1;
            float m01 = fminf(C[0][a] + C[1][b], C[0][b] + C[1][a]);
            float m23 = fminf(C[2][c] + C[3][d], C[2][d] + C[3][c]);
            best = fminf(best, m01 + m23);
        }
        rmse = sqrtf(best * 0.25f);
    }

    // ---- block reduce (deterministic fixed tree) ----
    s_red[tid] = rmse;
    __syncthreads();
    #pragma unroll
    for (int o = NTHREAD / 2; o; o >>= 1) {
        if (tid < o) s_red[tid] += s_red[tid + o];
        __syncthreads();
    }
    if (tid == 0) {
        g_partials[blockIdx.x] = s_red[0];
        __threadfence();
        unsigned old = atomicAdd(&g_count, 1u);
        s_last = (old == NBLOCK - 1) ? 1 : 0;
    }
    __syncthreads();

    // ---- last block finishes: deterministic fixed-order tree over partials ----
    if (s_last) {
        __threadfence();
        float t = 0.0f;
        for (int i = tid; i < NBLOCK; i += NTHREAD)
            t += __ldcg(&g_partials[i]);
        s_red[tid] = t;
        __syncthreads();
        #pragma unroll
        for (int o = NTHREAD / 2; o; o >>= 1) {
            if (tid < o) s_red[tid] += s_red[tid + o];
            __syncthreads();
        }
        for (int i = 1 + tid; i < out_size; i += NTHREAD)
            out[i] = 0.0f;
        if (tid == 0) {
            out[0]  = s_red[0] * (1.0f / (float)BATCH);
            g_count = 0;                    // reset for next graph replay
        }
    }
}

extern "C" void kernel_launch(void* const* d_in, const int* in_sizes, int n_in,
                              void* d_out, int out_size)
{
    const float* logits = (const float*)d_in[0];
    const int*   labels = (const int*)d_in[1];
    (void)in_sizes; (void)n_in;

    rmspe_kernel<<<NBLOCK, NTHREAD>>>(logits, labels, (float*)d_out, out_size);
}

// round 17
// speedup vs baseline: 1.2169x; 1.2169x over previous
#include <cuda_runtime.h>

// ---------------------------------------------------------------------------
// RMSPELoss: per-row permutation-invariant RMSE between logits[:, :4] (DoA
// estimates, radians) and the angles of the 4 one-hot label positions.
//
//   inputs  : d_in[0] = logits  float32 [131072, 181]
//             d_in[1] = labels  int32   [131072, 181]  (exactly 4 ones/row)
//   output  : mean over rows of sqrt(min_perm total / 4)
//
// R16: thread:row ratio 4 (TILE=64 rows scanned by 256 threads, 2048
// blocks = 1.73x oversubscription keeps every SM at its 8-resident-block
// register cap for the whole run). NO logit-load hoisting (R13 showed it
// costs 4+ registers and the blocks/SM cap). Algorithm unchanged from R12:
// flat int4 tile scan + smem scatter + thread-per-row 2+2 assignment DP +
// fused deterministic last-block reduction.
// ---------------------------------------------------------------------------

constexpr int   BATCH    = 131072;
constexpr int   NC       = 181;
constexpr int   TILE     = 64;                  // rows per block
constexpr int   NTHREAD  = 256;                 // 4x threads per row
constexpr int   NBLOCK   = BATCH / TILE;        // 2048
constexpr int   TILE_I4  = TILE * NC / 4;       // 2896 int4 per tile (exact)
// 2896 = 256*11 + 80  ->  2 batched sweeps of 5 + 1 full + 1 guarded (tid<80)
constexpr int   TAIL     = TILE_I4 - 11 * NTHREAD;      // 80

constexpr float PI_F      = 3.14159265358979323846f;
constexpr float TWO_PI_F  = 6.283185307179586f;
constexpr float INV_2PI_F = 0.15915494309189535f;    // 1/(2*pi)
constexpr float DEG2RAD_F = 0.017453292519943295f;   // pi/180
// d - (p-90)*deg2rad + pi == fma(p, -deg2rad, d + SHIFT)
constexpr float SHIFT_F   = 90.0f * DEG2RAD_F + PI_F;

// Static scratch (no allocation allowed).
__device__ float    g_partials[NBLOCK];
__device__ unsigned g_count = 0;                // self-resets each launch

// squared wrapped difference; bi = d_i + SHIFT already folded.
__device__ __forceinline__ float sqwrap2(float bi, float pj) {
    float x = fmaf(pj, -DEG2RAD_F, bi);
    float q = floorf(x * INV_2PI_F);
    float w = fmaf(-q, TWO_PI_F, x) - PI_F;
    return w * w;
}

__global__ __launch_bounds__(NTHREAD)
void rmspe_kernel(const float* __restrict__ logits, const int* __restrict__ labels,
                  float* __restrict__ out, int out_size)
{
    __shared__ int      s_cnt[TILE];
    __shared__ unsigned s_posw[TILE];
    __shared__ float    s_red[NTHREAD];
    __shared__ int      s_last;

    const int tid = threadIdx.x;
    const int r0  = blockIdx.x * TILE;

    if (tid < TILE) s_cnt[tid] = 0;
    __syncthreads();

    unsigned char* s_posb = (unsigned char*)s_posw;
    const int4* base = (const int4*)(labels + (long)r0 * NC);   // 16B aligned

    // ---- Phase A: flat vectorized scan, scatter one-positions ----
    auto emit = [&](int f) {                     // f = flat int index in tile
        unsigned rr = (unsigned)f / 181u;        // row within tile
        unsigned cc = (unsigned)f - rr * 181u;   // column (0..180)
        int rank = atomicAdd(&s_cnt[rr], 1);
        s_posb[rr * 4 + rank] = (unsigned char)cc;
    };
    auto sift = [&](int4 w, int i4) {            // i4 = int4 index in tile
        if (w.x | w.y | w.z | w.w) {
            int f = i4 * 4;
            if (w.x) emit(f);
            if (w.y) emit(f + 1);
            if (w.z) emit(f + 2);
            if (w.w) emit(f + 3);
        }
    };

    #pragma unroll 1
    for (int j = 0; j < 10; j += 5) {
        int4 v[5];
        #pragma unroll
        for (int u = 0; u < 5; u++)
            v[u] = __ldcs(base + tid + NTHREAD * (j + u));
        #pragma unroll
        for (int u = 0; u < 5; u++)
            sift(v[u], tid + NTHREAD * (j + u));
    }
    {
        int4 v10 = __ldcs(base + tid + NTHREAD * 10);
        int4 v11 = make_int4(0, 0, 0, 0);
        if (tid < TAIL) v11 = __ldcs(base + tid + NTHREAD * 11);
        sift(v10, tid + NTHREAD * 10);
        sift(v11, tid + NTHREAD * 11);
    }
    __syncthreads();

    // ---- Phase B: threads 0-63, one row each: cost matrix + 2+2 DP ----
    float rmse = 0.0f;
    if (tid < TILE) {
        const unsigned pw = s_posw[tid];
        const float* lg = logits + (long)(r0 + tid) * NC;
        const float b0 = __ldcs(lg)     + SHIFT_F;
        const float b1 = __ldcs(lg + 1) + SHIFT_F;
        const float b2 = __ldcs(lg + 2) + SHIFT_F;
        const float b3 = __ldcs(lg + 3) + SHIFT_F;

        float pj[4];
        pj[0] = (float)( pw        & 0xFFu);
        pj[1] = (float)((pw >>  8) & 0xFFu);
        pj[2] = (float)((pw >> 16) & 0xFFu);
        pj[3] = (float)((pw >> 24) & 0xFFu);

        float C[4][4];
        #pragma unroll
        for (int j = 0; j < 4; j++) {
            C[0][j] = sqwrap2(b0, pj[j]);
            C[1][j] = sqwrap2(b1, pj[j]);
            C[2][j] = sqwrap2(b2, pj[j]);
            C[3][j] = sqwrap2(b3, pj[j]);
        }

        // min over all 24 perms = min over 6 unordered column pairs for
        // rows {0,1} x 2 orderings x 2 orderings of the complement.
        float best = 3.4e38f;
        #pragma unroll
        for (int s = 0; s < 6; s++) {
            const int a = (s < 3) ? 0 : (s < 5) ? 1 : 2;
            const int b = (s == 0) ? 1 : (s == 1 || s == 3) ? 2 : 3;
            const int c = (s == 5) ? 0 : (s >= 3) ? 0 : (s == 0) ? 2 : 1;
            const int d = (s == 0) ? 3 : (s == 1) ? 3 : (s == 2) ? 2 :
                          (s == 3) ? 3 : (s == 4) ? 2 : 1;
            float m01 = fminf(C[0][a] + C[1][b], C[0][b] + C[1][a]);
            float m23 = fminf(C[2][c] + C[3][d], C[2][d] + C[3][c]);
            best = fminf(best, m01 + m23);
        }
        rmse = sqrtf(best * 0.25f);
    }

    // ---- block reduce (deterministic fixed tree over all 256 threads) ----
    s_red[tid] = rmse;
    __syncthreads();
    #pragma unroll
    for (int o = NTHREAD / 2; o; o >>= 1) {
        if (tid < o) s_red[tid] += s_red[tid + o];
        __syncthreads();
    }
    if (tid == 0) {
        g_partials[blockIdx.x] = s_red[0];
        __threadfence();
        unsigned old = atomicAdd(&g_count, 1u);
        s_last = (old == NBLOCK - 1) ? 1 : 0;
    }
    __syncthreads();

    // ---- last block finishes: deterministic fixed-order tree over partials ----
    if (s_last) {
        __threadfence();
        float t = 0.0f;
        for (int i = tid; i < NBLOCK; i += NTHREAD)
            t += __ldcg(&g_partials[i]);
        s_red[tid] = t;
        __syncthreads();
        #pragma unroll
        for (int o = NTHREAD / 2; o; o >>= 1) {
            if (tid < o) s_red[tid] += s_red[tid + o];
            __syncthreads();
        }
        for (int i = 1 + tid; i < out_size; i += NTHREAD)
            out[i] = 0.0f;
        if (tid == 0) {
            out[0]  = s_red[0] * (1.0f / (float)BATCH);
            g_count = 0;                    // reset for next graph replay
        }
    }
}

extern "C" void kernel_launch(void* const* d_in, const int* in_sizes, int n_in,
                              void* d_out, int out_size)
{
    const float* logits = (const float*)d_in[0];
    const int*   labels = (const int*)d_in[1];
    (void)in_sizes; (void)n_in;

    rmspe_kernel<<<NBLOCK, NTHREAD>>>(logits, labels, (float*)d_out, out_size);
}